// round 14
// baseline (speedup 1.0000x reference)
#include <cuda_runtime.h>
#include <cuda_fp16.h>
#include <cstdint>
#include <math.h>

#define DM 2048
#define DF 8192
#define NT 8192
#define KH 8192   // split-K half of GEMM2's K = 2*DF

// ---------------- scratch ----------------
__device__ __align__(256) __half g_X[(size_t)NT * DM];           // [M][K]
__device__ __align__(256) __half g_H[(size_t)NT * 2 * DF];       // [M][2*DF] gate pre-scaled
__device__ __align__(256) __half g_W1h[(size_t)DM * 2 * DF];     // [DM][2*DF]  (K x N, concat)
__device__ __align__(256) __half g_W2h[(size_t)2 * DF * DM];     // [2*DF][DM]  (K x N, stacked)
__device__ __align__(256) float  g_P[2 * (size_t)NT * DM];       // split-K partials
__device__ float g_gate[2 * NT];

// ---------------- helpers ----------------
__device__ __forceinline__ uint32_t smem_u32(const void* p) {
    uint32_t a;
    asm("{ .reg .u64 t; cvta.to.shared.u64 t, %1; cvt.u32.u64 %0, t; }" : "=r"(a) : "l"(p));
    return a;
}
#define CP_ASYNC16(sa, g) \
    asm volatile("cp.async.cg.shared.global [%0], [%1], 16;" :: "r"(sa), "l"(g))
#define CP_COMMIT() asm volatile("cp.async.commit_group;" ::: "memory")
#define CP_WAIT(n)  asm volatile("cp.async.wait_group %0;" :: "n"(n) : "memory")

#define LDSM_X4(r0, r1, r2, r3, a) \
    asm volatile("ldmatrix.sync.aligned.m8n8.x4.shared.b16 {%0,%1,%2,%3}, [%4];" \
                 : "=r"(r0), "=r"(r1), "=r"(r2), "=r"(r3) : "r"(a))
#define LDSM_X4T(r0, r1, r2, r3, a) \
    asm volatile("ldmatrix.sync.aligned.m8n8.x4.trans.shared.b16 {%0,%1,%2,%3}, [%4];" \
                 : "=r"(r0), "=r"(r1), "=r"(r2), "=r"(r3) : "r"(a))

__device__ __forceinline__ void mma16816(float* d, const uint32_t* a, const uint32_t* b) {
    asm volatile(
        "mma.sync.aligned.m16n8k16.row.col.f32.f16.f16.f32 "
        "{%0,%1,%2,%3}, {%4,%5,%6,%7}, {%8,%9}, {%0,%1,%2,%3};"
        : "+f"(d[0]), "+f"(d[1]), "+f"(d[2]), "+f"(d[3])
        : "r"(a[0]), "r"(a[1]), "r"(a[2]), "r"(a[3]), "r"(b[0]), "r"(b[1]));
}

// A tiles: 128B rows (8x16B segs); B tiles: 256B rows (16x16B segs). XOR-of-row swizzle.
__device__ __forceinline__ uint32_t swzA(uint32_t r, uint32_t s) {
    return (r << 7) + ((s ^ (r & 7)) << 4);
}
__device__ __forceinline__ uint32_t swzB(uint32_t r, uint32_t s) {
    return (r << 8) + ((s ^ (r & 7)) << 4);
}
__device__ __forceinline__ uint32_t pack_h2(float a, float b) {
    __half2 v = __floats2half2_rn(a, b);
    return *reinterpret_cast<uint32_t*>(&v);
}

// fast erf: Abramowitz-Stegun 7.1.26, |err| <= 1.5e-7
__device__ __forceinline__ float erf_fast(float x) {
    float ax = fabsf(x);
    float t = __fdividef(1.0f, fmaf(0.3275911f, ax, 1.0f));
    float p = fmaf(t, 1.061405429f, -1.453152027f);
    p = fmaf(t, p, 1.421413741f);
    p = fmaf(t, p, -0.284496736f);
    p = fmaf(t, p, 0.254829592f);
    p = p * t;
    float e = __expf(-ax * ax);
    return copysignf(fmaf(-p, e, 1.0f), x);
}
__device__ __forceinline__ float gelu_f(float v) {
    return 0.5f * v * (1.0f + erf_fast(v * 0.70710678118654752f));
}

// ---------------- prep kernels ----------------
__global__ void gate_k(const int* __restrict__ ids, const float* __restrict__ w,
                       float* __restrict__ gate) {
    int i = blockIdx.x * blockDim.x + threadIdx.x;
    if (i >= NT) return;
    int a = ids[2 * i] & 1, b = ids[2 * i + 1] & 1;
    float wa = w[2 * i], wb = w[2 * i + 1];
    gate[i]      = (a ? 0.f : wa) + (b ? 0.f : wb);
    gate[NT + i] = (a ? wa : 0.f) + (b ? wb : 0.f);
}

__global__ void conv_k(const float4* __restrict__ x4, uint2* __restrict__ o, size_t n4) {
    size_t i = (size_t)blockIdx.x * blockDim.x + threadIdx.x;
    if (i >= n4) return;
    float4 v = x4[i];
    uint2 r;
    r.x = pack_h2(v.x, v.y);
    r.y = pack_h2(v.z, v.w);
    o[i] = r;
}

// W1_e [DM][DF] f32 -> W1h [DM][2*DF] fp16 at column offset e*DF (blockIdx.z = e)
__global__ void conv_w1(const float4* __restrict__ W0, const float4* __restrict__ W1,
                        uint2* __restrict__ out) {
    size_t i = (size_t)blockIdx.x * blockDim.x + threadIdx.x;
    const size_t row_u4 = DF / 4;
    if (i >= (size_t)DM * row_u4) return;
    int e = blockIdx.z;
    float4 v = e ? W1[i] : W0[i];
    size_t k = i / row_u4, n4 = i % row_u4;
    uint2 r;
    r.x = pack_h2(v.x, v.y);
    r.y = pack_h2(v.z, v.w);
    out[k * (2 * DF / 4) + (size_t)e * (DF / 4) + n4] = r;
}

// W2_e [DF][DM] f32 -> W2h rows [e*DF .. e*DF+DF)
__global__ void conv_w2(const float4* __restrict__ W0, const float4* __restrict__ W1,
                        uint2* __restrict__ out) {
    size_t i = (size_t)blockIdx.x * blockDim.x + threadIdx.x;
    if (i >= (size_t)DF * DM / 4) return;
    int e = blockIdx.z;
    float4 v = e ? W1[i] : W0[i];
    uint2 r;
    r.x = pack_h2(v.x, v.y);
    r.y = pack_h2(v.z, v.w);
    out[(size_t)e * (DF * DM / 4) + i] = r;
}

// split-K reduce: out = P0 + P1 + g0*b2_0 + g1*b2_1  (float4 over NT*DM)
__global__ void reduce_k(const float4* __restrict__ P0, const float4* __restrict__ P1,
                         const float4* __restrict__ b20, const float4* __restrict__ b21,
                         const float* __restrict__ gate, float4* __restrict__ out) {
    size_t i = (size_t)blockIdx.x * blockDim.x + threadIdx.x;
    if (i >= (size_t)NT * DM / 4) return;
    int row = (int)(i / (DM / 4));
    int c4  = (int)(i % (DM / 4));
    float g0 = gate[row], g1 = gate[NT + row];
    float4 p = P0[i], q = P1[i], a = b20[c4], b = b21[c4];
    float4 r;
    r.x = p.x + q.x + g0 * a.x + g1 * b.x;
    r.y = p.y + q.y + g0 * a.y + g1 * b.y;
    r.z = p.z + q.z + g0 * a.z + g1 * b.z;
    r.w = p.w + q.w + g0 * a.w + g1 * b.w;
    out[i] = r;
}

// -- fp16 mma.sync GEMM: CTA 128x128, BK=64, 256 thr (8 warps, warp 32x64), 2 CTAs/SM --
static constexpr int BM = 128, BN = 128, BK = 64;
static constexpr int STAGES = 3;
static constexpr int A_TILE_B = BM * 128;             // [M=128][K=64], 128B rows = 16 KB
static constexpr int B_TILE_B = BK * 256;             // [K=64][N=128], 256B rows = 16 KB
static constexpr int STAGE_B = A_TILE_B + B_TILE_B;   // 32768
static constexpr int SMEM_BYTES = STAGES * STAGE_B;   // 98304 (x2 CTAs = 196608/SM)
static constexpr int O_A = 0, O_B = A_TILE_B;
static constexpr int NTHR = 256;

__device__ __forceinline__ void load_A(uint32_t sdst, const __half* __restrict__ g,
                                       int ld, int t) {
#pragma unroll
    for (int i = 0; i < 4; i++) {                 // 128 rows x 8 segs / 256 thr
        uint32_t idx = t + i * NTHR;
        uint32_t r = idx >> 3, s = idx & 7;
        CP_ASYNC16(sdst + swzA(r, s), g + (size_t)r * ld + s * 8);
    }
}
__device__ __forceinline__ void load_B(uint32_t sdst, const __half* __restrict__ g,
                                       int ld, int t) {
#pragma unroll
    for (int i = 0; i < 4; i++) {                 // 64 rows x 16 segs / 256 thr
        uint32_t idx = t + i * NTHR;
        uint32_t r = idx >> 4, s = idx & 15;
        CP_ASYNC16(sdst + swzB(r, s), g + (size_t)r * ld + s * 8);
    }
}

// EPI 0 (GEMM1): Ch[row][col] = fp16(gate_e[row]*GELU(v + b1_e[col - e*DF])), e = bx>=n_split
// EPI 2 (GEMM2 split-K): Cf[z][row][col] = raw v; K-range z*KH..(z+1)*KH, reversed bm
template <int EPI>
__global__ void __launch_bounds__(NTHR, 2)
moe_gemm(const __half* __restrict__ A, const __half* __restrict__ B,
         const float* __restrict__ bias0, const float* __restrict__ bias1,
         const float* __restrict__ gate,
         float* __restrict__ Cf, __half* __restrict__ Ch,
         int K, int lda, int ldb, int ldc, int n_split) {
    extern __shared__ char smem[];
    const uint32_t sb = smem_u32(smem);
    const int t = threadIdx.x, wid = t >> 5, lid = t & 31;
    const int wm = wid >> 1, wn = wid & 1;        // 4m x 2n warps, warp tile 32x64
    const int by = (EPI == 2) ? (gridDim.y - 1 - blockIdx.y) : blockIdx.y;
    const int bm = by * BM, bn = blockIdx.x * BN;
    const int NC = K / BK;
    const int ex = (EPI == 0) ? (blockIdx.x >= n_split) : 0;
    const size_t koff = (EPI == 2) ? (size_t)blockIdx.z * KH : 0;

    const __half* a_g = A + (size_t)bm * lda + koff;
    const __half* b_g = B + koff * ldb + bn;
    float* Co = (EPI == 2) ? Cf + (size_t)blockIdx.z * NT * DM : Cf;

    float acc[2][8][4];
#pragma unroll
    for (int i = 0; i < 2; i++)
#pragma unroll
        for (int j = 0; j < 8; j++)
#pragma unroll
            for (int q = 0; q < 4; q++) acc[i][j][q] = 0.f;

#pragma unroll
    for (int p = 0; p < STAGES - 1; p++) {
        uint32_t st = sb + p * STAGE_B;
        load_A(st + O_A, a_g + p * BK, lda, t);
        load_B(st + O_B, b_g + (size_t)p * BK * ldb, ldb, t);
        CP_COMMIT();
    }

    // A frags (non-trans, [M][K] 128B rows)
    const uint32_t a_r = (uint32_t)(lid & 15);
    const uint32_t a_s = (uint32_t)(lid >> 4);
    // B frags (trans, [K][N] 256B rows); seg units of 16B
    const uint32_t bk_r = (uint32_t)((lid & 7) + ((lid >> 3) & 1) * 8);
    const uint32_t bn_s = (uint32_t)(lid >> 4);

    for (int c = 0; c < NC; c++) {
        CP_WAIT(STAGES - 2);
        __syncthreads();
        if (c + STAGES - 1 < NC) {
            int cc = c + STAGES - 1;
            uint32_t st = sb + (cc % STAGES) * STAGE_B;
            load_A(st + O_A, a_g + cc * BK, lda, t);
            load_B(st + O_B, b_g + (size_t)cc * BK * ldb, ldb, t);
        }
        CP_COMMIT();

        const uint32_t st = sb + (c % STAGES) * STAGE_B;
#pragma unroll
        for (int kk = 0; kk < 4; kk++) {
            uint32_t ah[2][4], bh[4][4];
#pragma unroll
            for (int mt = 0; mt < 2; mt++) {
                uint32_t off = swzA(wm * 32 + mt * 16 + a_r, kk * 2 + a_s);
                LDSM_X4(ah[mt][0], ah[mt][1], ah[mt][2], ah[mt][3], st + O_A + off);
            }
#pragma unroll
            for (int p = 0; p < 4; p++) {   // 4 n16 groups = warp's 64 cols
                uint32_t off = swzB(kk * 16 + bk_r, wn * 8 + p * 2 + bn_s);
                LDSM_X4T(bh[p][0], bh[p][1], bh[p][2], bh[p][3], st + O_B + off);
            }
#pragma unroll
            for (int mt = 0; mt < 2; mt++)
#pragma unroll
                for (int nt = 0; nt < 8; nt++)
                    mma16816(acc[mt][nt], ah[mt], &bh[nt >> 1][(nt & 1) << 1]);
        }
    }

    // ---------------- epilogue ----------------
    const int lr = lid >> 2, lc = (lid & 3) << 1;
#pragma unroll
    for (int mt = 0; mt < 2; mt++) {
        int row0 = bm + wm * 32 + mt * 16 + lr;
        float ga0 = 0.f, ga1 = 0.f;
        if (EPI == 0) {
            ga0 = gate[ex * NT + row0];
            ga1 = gate[ex * NT + row0 + 8];
        }
#pragma unroll
        for (int nt = 0; nt < 8; nt++) {
            int col = bn + wn * 64 + nt * 8 + lc;
            float b00 = 0.f, b01 = 0.f;
            if (EPI == 0) {
                const float* ba = ex ? bias1 : bias0;
                int bc = col - ex * DF;
                b00 = ba[bc]; b01 = ba[bc + 1];
            }
#pragma unroll
            for (int h = 0; h < 2; h++) {
                int row = row0 + h * 8;
                size_t o = (size_t)row * ldc + col;
                if (EPI == 0) {
                    float g = h ? ga1 : ga0;
                    float v0 = g * gelu_f(acc[mt][nt][2 * h + 0] + b00);
                    float v1 = g * gelu_f(acc[mt][nt][2 * h + 1] + b01);
                    *reinterpret_cast<uint32_t*>(Ch + o) = pack_h2(v0, v1);
                } else {
                    float2 w;
                    w.x = acc[mt][nt][2 * h + 0];
                    w.y = acc[mt][nt][2 * h + 1];
                    *reinterpret_cast<float2*>(Co + o) = w;
                }
            }
        }
    }
}

// ---------------- launch ----------------
extern "C" void kernel_launch(void* const* d_in, const int* in_sizes, int n_in,
                              void* d_out, int out_size) {
    const float* x   = (const float*)d_in[0];
    const int*   ids = (const int*)d_in[1];
    const float* tw  = (const float*)d_in[2];
    const float* W1[2] = {(const float*)d_in[3], (const float*)d_in[7]};
    const float* b1[2] = {(const float*)d_in[4], (const float*)d_in[8]};
    const float* W2[2] = {(const float*)d_in[5], (const float*)d_in[9]};
    const float* b2[2] = {(const float*)d_in[6], (const float*)d_in[10]};
    float* out = (float*)d_out;

    __half *X, *H, *W1h, *W2h;
    float *gate, *P;
    cudaGetSymbolAddress((void**)&X, g_X);
    cudaGetSymbolAddress((void**)&H, g_H);
    cudaGetSymbolAddress((void**)&W1h, g_W1h);
    cudaGetSymbolAddress((void**)&W2h, g_W2h);
    cudaGetSymbolAddress((void**)&P, g_P);
    cudaGetSymbolAddress((void**)&gate, g_gate);

    cudaFuncSetAttribute(moe_gemm<0>, cudaFuncAttributeMaxDynamicSharedMemorySize, SMEM_BYTES);
    cudaFuncSetAttribute(moe_gemm<2>, cudaFuncAttributeMaxDynamicSharedMemorySize, SMEM_BYTES);

    gate_k<<<(NT + 255) / 256, 256>>>(ids, tw, gate);
    {
        size_t n4 = (size_t)NT * DM / 4;
        conv_k<<<(unsigned)((n4 + 255) / 256), 256>>>((const float4*)x, (uint2*)X, n4);
    }
    {
        size_t n4 = (size_t)DM * DF / 4;
        conv_w1<<<dim3((unsigned)((n4 + 255) / 256), 1, 2), 256>>>(
            (const float4*)W1[0], (const float4*)W1[1], (uint2*)W1h);
    }
    {
        size_t n4 = (size_t)DF * DM / 4;
        conv_w2<<<dim3((unsigned)((n4 + 255) / 256), 1, 2), 256>>>(
            (const float4*)W2[0], (const float4*)W2[1], (uint2*)W2h);
    }
    // GEMM1 merged: H [NT][2*DF], N = 16384, K = DM, grid (128, 64)
    moe_gemm<0><<<dim3(2 * DF / BN, NT / BM), NTHR, SMEM_BYTES>>>(
        X, W1h, b1[0], b1[1], gate, nullptr, H,
        DM, DM, 2 * DF, 2 * DF, DF / BN);
    // GEMM2 split-K=2: P[z] = H[:, z*KH:(z+1)*KH] @ W2h[z*KH:(z+1)*KH, :], grid (16, 64, 2)
    moe_gemm<2><<<dim3(DM / BN, NT / BM, 2), NTHR, SMEM_BYTES>>>(
        H, W2h, nullptr, nullptr, gate, P, nullptr,
        KH, 2 * DF, DM, DM, 1 << 30);
    // reduce: out = P0 + P1 + g0*b2_0 + g1*b2_1
    {
        size_t n4 = (size_t)NT * DM / 4;
        reduce_k<<<(unsigned)((n4 + 255) / 256), 256>>>(
            (const float4*)P, (const float4*)(P + (size_t)NT * DM),
            (const float4*)b2[0], (const float4*)b2[1], gate, (float4*)out);
    }
}

// round 15
// speedup vs baseline: 1.0086x; 1.0086x over previous
#include <cuda_runtime.h>
#include <cuda_fp16.h>
#include <cstdint>
#include <math.h>

#define DM 2048
#define DF 8192
#define NT 8192
#define KH 8192   // split-K half of GEMM2's K = 2*DF

// ---------------- scratch ----------------
__device__ __align__(256) __half g_X[(size_t)NT * DM];           // [M][K]
__device__ __align__(256) __half g_H[(size_t)NT * 2 * DF];       // [M][2*DF] gate pre-scaled
__device__ __align__(256) __half g_W1h[(size_t)DM * 2 * DF];     // [DM][2*DF]  (K x N, concat)
__device__ __align__(256) __half g_W2h[(size_t)2 * DF * DM];     // [2*DF][DM]  (K x N, stacked)
__device__ __align__(256) float  g_P[2 * (size_t)NT * DM];       // split-K partials
__device__ float g_gate[2 * NT];

// ---------------- helpers ----------------
__device__ __forceinline__ uint32_t smem_u32(const void* p) {
    uint32_t a;
    asm("{ .reg .u64 t; cvta.to.shared.u64 t, %1; cvt.u32.u64 %0, t; }" : "=r"(a) : "l"(p));
    return a;
}
#define CP_ASYNC16(sa, g) \
    asm volatile("cp.async.cg.shared.global [%0], [%1], 16;" :: "r"(sa), "l"(g))
#define CP_COMMIT() asm volatile("cp.async.commit_group;" ::: "memory")
#define CP_WAIT(n)  asm volatile("cp.async.wait_group %0;" :: "n"(n) : "memory")

#define LDSM_X4(r0, r1, r2, r3, a) \
    asm volatile("ldmatrix.sync.aligned.m8n8.x4.shared.b16 {%0,%1,%2,%3}, [%4];" \
                 : "=r"(r0), "=r"(r1), "=r"(r2), "=r"(r3) : "r"(a))
#define LDSM_X4T(r0, r1, r2, r3, a) \
    asm volatile("ldmatrix.sync.aligned.m8n8.x4.trans.shared.b16 {%0,%1,%2,%3}, [%4];" \
                 : "=r"(r0), "=r"(r1), "=r"(r2), "=r"(r3) : "r"(a))

__device__ __forceinline__ void mma16816(float* d, const uint32_t* a, const uint32_t* b) {
    asm volatile(
        "mma.sync.aligned.m16n8k16.row.col.f32.f16.f16.f32 "
        "{%0,%1,%2,%3}, {%4,%5,%6,%7}, {%8,%9}, {%0,%1,%2,%3};"
        : "+f"(d[0]), "+f"(d[1]), "+f"(d[2]), "+f"(d[3])
        : "r"(a[0]), "r"(a[1]), "r"(a[2]), "r"(a[3]), "r"(b[0]), "r"(b[1]));
}

// A tiles: 128B rows (8x16B segs); B tiles: 512B rows (32x16B segs). XOR-of-row swizzle.
__device__ __forceinline__ uint32_t swzA(uint32_t r, uint32_t s) {
    return (r << 7) + ((s ^ (r & 7)) << 4);
}
__device__ __forceinline__ uint32_t swzB(uint32_t r, uint32_t s) {
    return (r << 9) + ((s ^ (r & 7)) << 4);
}
__device__ __forceinline__ uint32_t pack_h2(float a, float b) {
    __half2 v = __floats2half2_rn(a, b);
    return *reinterpret_cast<uint32_t*>(&v);
}

// fast erf: Abramowitz-Stegun 7.1.26, |err| <= 1.5e-7
__device__ __forceinline__ float erf_fast(float x) {
    float ax = fabsf(x);
    float t = __fdividef(1.0f, fmaf(0.3275911f, ax, 1.0f));
    float p = fmaf(t, 1.061405429f, -1.453152027f);
    p = fmaf(t, p, 1.421413741f);
    p = fmaf(t, p, -0.284496736f);
    p = fmaf(t, p, 0.254829592f);
    p = p * t;
    float e = __expf(-ax * ax);
    return copysignf(fmaf(-p, e, 1.0f), x);
}
__device__ __forceinline__ float gelu_f(float v) {
    return 0.5f * v * (1.0f + erf_fast(v * 0.70710678118654752f));
}

// ---------------- prep kernels ----------------
__global__ void gate_k(const int* __restrict__ ids, const float* __restrict__ w,
                       float* __restrict__ gate) {
    int i = blockIdx.x * blockDim.x + threadIdx.x;
    if (i >= NT) return;
    int a = ids[2 * i] & 1, b = ids[2 * i + 1] & 1;
    float wa = w[2 * i], wb = w[2 * i + 1];
    gate[i]      = (a ? 0.f : wa) + (b ? 0.f : wb);
    gate[NT + i] = (a ? wa : 0.f) + (b ? wb : 0.f);
}

__global__ void conv_k(const float4* __restrict__ x4, uint2* __restrict__ o, size_t n4) {
    size_t i = (size_t)blockIdx.x * blockDim.x + threadIdx.x;
    if (i >= n4) return;
    float4 v = x4[i];
    uint2 r;
    r.x = pack_h2(v.x, v.y);
    r.y = pack_h2(v.z, v.w);
    o[i] = r;
}

// W1_e [DM][DF] f32 -> W1h [DM][2*DF] fp16 at column offset e*DF (blockIdx.z = e)
__global__ void conv_w1(const float4* __restrict__ W0, const float4* __restrict__ W1,
                        uint2* __restrict__ out) {
    size_t i = (size_t)blockIdx.x * blockDim.x + threadIdx.x;
    const size_t row_u4 = DF / 4;
    if (i >= (size_t)DM * row_u4) return;
    int e = blockIdx.z;
    float4 v = e ? W1[i] : W0[i];
    size_t k = i / row_u4, n4 = i % row_u4;
    uint2 r;
    r.x = pack_h2(v.x, v.y);
    r.y = pack_h2(v.z, v.w);
    out[k * (2 * DF / 4) + (size_t)e * (DF / 4) + n4] = r;
}

// W2_e [DF][DM] f32 -> W2h rows [e*DF .. e*DF+DF)
__global__ void conv_w2(const float4* __restrict__ W0, const float4* __restrict__ W1,
                        uint2* __restrict__ out) {
    size_t i = (size_t)blockIdx.x * blockDim.x + threadIdx.x;
    if (i >= (size_t)DF * DM / 4) return;
    int e = blockIdx.z;
    float4 v = e ? W1[i] : W0[i];
    uint2 r;
    r.x = pack_h2(v.x, v.y);
    r.y = pack_h2(v.z, v.w);
    out[(size_t)e * (DF * DM / 4) + i] = r;
}

// split-K reduce: out = P0 + P1 + g0*b2_0 + g1*b2_1  (float4 over NT*DM)
__global__ void reduce_k(const float4* __restrict__ P0, const float4* __restrict__ P1,
                         const float4* __restrict__ b20, const float4* __restrict__ b21,
                         const float* __restrict__ gate, float4* __restrict__ out) {
    size_t i = (size_t)blockIdx.x * blockDim.x + threadIdx.x;
    if (i >= (size_t)NT * DM / 4) return;
    int row = (int)(i / (DM / 4));
    int c4  = (int)(i % (DM / 4));
    float g0 = gate[row], g1 = gate[NT + row];
    float4 p = P0[i], q = P1[i], a = b20[c4], b = b21[c4];
    float4 r;
    r.x = p.x + q.x + g0 * a.x + g1 * b.x;
    r.y = p.y + q.y + g0 * a.y + g1 * b.y;
    r.z = p.z + q.z + g0 * a.z + g1 * b.z;
    r.w = p.w + q.w + g0 * a.w + g1 * b.w;
    out[i] = r;
}

// ------------- fp16 mma.sync GEMM: CTA 128x256, BK=64, 512 thr, B in [K][N] -------------
static constexpr int BM = 128, BN = 256, BK = 64;
static constexpr int STAGES = 4;
static constexpr int A_TILE_B = BM * 128;
static constexpr int B_TILE_B = BK * 512;
static constexpr int STAGE_B = A_TILE_B + B_TILE_B;   // 49152
static constexpr int SMEM_BYTES = STAGES * STAGE_B;   // 196608
static constexpr int O_A = 0, O_B = A_TILE_B;
static constexpr int NTHR = 512;

__device__ __forceinline__ void load_A(uint32_t sdst, const __half* __restrict__ g,
                                       int ld, int t) {
#pragma unroll
    for (int i = 0; i < 2; i++) {
        uint32_t idx = t + i * NTHR;
        uint32_t r = idx >> 3, s = idx & 7;
        CP_ASYNC16(sdst + swzA(r, s), g + (size_t)r * ld + s * 8);
    }
}
__device__ __forceinline__ void load_B(uint32_t sdst, const __half* __restrict__ g,
                                       int ld, int t) {
#pragma unroll
    for (int i = 0; i < 4; i++) {
        uint32_t idx = t + i * NTHR;
        uint32_t r = idx >> 5, s = idx & 31;
        CP_ASYNC16(sdst + swzB(r, s), g + (size_t)r * ld + s * 8);
    }
}

// EPI 0 (GEMM1): Ch[row][col] = fp16(gate_e[row]*GELU(v + b1_e[col - e*DF])), e = bx>=n_split
// EPI 2 (GEMM2 split-K): Cf[z][row][col] = raw v; K-range z*KH..(z+1)*KH, reversed bm
template <int EPI>
__global__ void __launch_bounds__(NTHR, 1)
moe_gemm(const __half* __restrict__ A, const __half* __restrict__ B,
         const float* __restrict__ bias0, const float* __restrict__ bias1,
         const float* __restrict__ gate,
         float* __restrict__ Cf, __half* __restrict__ Ch,
         int K, int lda, int ldb, int ldc, int n_split) {
    extern __shared__ char smem[];
    const uint32_t sb = smem_u32(smem);
    const int t = threadIdx.x, wid = t >> 5, lid = t & 31;
    const int wm = wid >> 2, wn = wid & 3;        // 4x4 warps, warp tile 32x64
    const int by = (EPI == 2) ? (gridDim.y - 1 - blockIdx.y) : blockIdx.y;
    const int bm = by * BM, bn = blockIdx.x * BN;
    const int NC = K / BK;
    const int ex = (EPI == 0) ? (blockIdx.x >= n_split) : 0;
    const size_t koff = (EPI == 2) ? (size_t)blockIdx.z * KH : 0;

    const __half* a_g = A + (size_t)bm * lda + koff;
    const __half* b_g = B + koff * ldb + bn;
    float* Co = (EPI == 2) ? Cf + (size_t)blockIdx.z * NT * DM : Cf;

    float acc[2][8][4];
#pragma unroll
    for (int i = 0; i < 2; i++)
#pragma unroll
        for (int j = 0; j < 8; j++)
#pragma unroll
            for (int q = 0; q < 4; q++) acc[i][j][q] = 0.f;

#pragma unroll
    for (int p = 0; p < STAGES - 1; p++) {
        uint32_t st = sb + p * STAGE_B;
        load_A(st + O_A, a_g + p * BK, lda, t);
        load_B(st + O_B, b_g + (size_t)p * BK * ldb, ldb, t);
        CP_COMMIT();
    }

    // A frags (non-trans, [M][K] 128B rows)
    const uint32_t a_r = (uint32_t)(lid & 15);
    const uint32_t a_s = (uint32_t)(lid >> 4);
    // B frags (trans, [K][N] 512B rows)
    const uint32_t bk_r = (uint32_t)((lid & 7) + ((lid >> 3) & 1) * 8);
    const uint32_t bn_s = (uint32_t)(lid >> 4);

    for (int c = 0; c < NC; c++) {
        CP_WAIT(STAGES - 2);
        __syncthreads();
        if (c + STAGES - 1 < NC) {
            int cc = c + STAGES - 1;
            uint32_t st = sb + (cc % STAGES) * STAGE_B;
            load_A(st + O_A, a_g + cc * BK, lda, t);
            load_B(st + O_B, b_g + (size_t)cc * BK * ldb, ldb, t);
        }
        CP_COMMIT();

        const uint32_t st = sb + (c % STAGES) * STAGE_B;

        // 8-step software pipeline: step s = (kk, h2); B in n32 halves, ping-pong frags.
        uint32_t aF[2][2][4];   // [kk&1][mt][4]
        uint32_t bF[2][2][4];   // [s&1][pp][4]  (pp = n16 group within half)

        // preload step 0: A(kk=0), B(kk=0, half 0)
#pragma unroll
        for (int mt = 0; mt < 2; mt++) {
            uint32_t off = swzA(wm * 32 + mt * 16 + a_r, a_s);
            LDSM_X4(aF[0][mt][0], aF[0][mt][1], aF[0][mt][2], aF[0][mt][3], st + O_A + off);
        }
#pragma unroll
        for (int pp = 0; pp < 2; pp++) {
            uint32_t off = swzB(bk_r, wn * 8 + pp * 2 + bn_s);
            LDSM_X4T(bF[0][pp][0], bF[0][pp][1], bF[0][pp][2], bF[0][pp][3], st + O_B + off);
        }

#pragma unroll
        for (int s = 0; s < 8; s++) {
            const int kk = s >> 1, h2 = s & 1;
            if (s + 1 < 8) {   // prefetch frags for step s+1
                const int nkk = (s + 1) >> 1, nh2 = (s + 1) & 1;
#pragma unroll
                for (int pp = 0; pp < 2; pp++) {
                    uint32_t off = swzB(nkk * 16 + bk_r, wn * 8 + (nh2 * 2 + pp) * 2 + bn_s);
                    LDSM_X4T(bF[(s + 1) & 1][pp][0], bF[(s + 1) & 1][pp][1],
                             bF[(s + 1) & 1][pp][2], bF[(s + 1) & 1][pp][3], st + O_B + off);
                }
                if (nh2 == 0) {
#pragma unroll
                    for (int mt = 0; mt < 2; mt++) {
                        uint32_t off = swzA(wm * 32 + mt * 16 + a_r, nkk * 2 + a_s);
                        LDSM_X4(aF[nkk & 1][mt][0], aF[nkk & 1][mt][1],
                                aF[nkk & 1][mt][2], aF[nkk & 1][mt][3], st + O_A + off);
                    }
                }
            }
#pragma unroll
            for (int mt = 0; mt < 2; mt++)
#pragma unroll
                for (int ntl = 0; ntl < 4; ntl++)
                    mma16816(acc[mt][h2 * 4 + ntl], aF[kk & 1][mt],
                             &bF[s & 1][ntl >> 1][(ntl & 1) << 1]);
        }
    }

    // ---------------- epilogue ----------------
    const int lr = lid >> 2, lc = (lid & 3) << 1;
#pragma unroll
    for (int mt = 0; mt < 2; mt++) {
        int row0 = bm + wm * 32 + mt * 16 + lr;
        float ga0 = 0.f, ga1 = 0.f;
        if (EPI == 0) {
            ga0 = gate[ex * NT + row0];
            ga1 = gate[ex * NT + row0 + 8];
        }
#pragma unroll
        for (int nt = 0; nt < 8; nt++) {
            int col = bn + wn * 64 + nt * 8 + lc;
            float b00 = 0.f, b01 = 0.f;
            if (EPI == 0) {
                const float* ba = ex ? bias1 : bias0;
                int bc = col - ex * DF;
                b00 = ba[bc]; b01 = ba[bc + 1];
            }
#pragma unroll
            for (int h = 0; h < 2; h++) {
                int row = row0 + h * 8;
                size_t o = (size_t)row * ldc + col;
                if (EPI == 0) {
                    float g = h ? ga1 : ga0;
                    float v0 = g * gelu_f(acc[mt][nt][2 * h + 0] + b00);
                    float v1 = g * gelu_f(acc[mt][nt][2 * h + 1] + b01);
                    *reinterpret_cast<uint32_t*>(Ch + o) = pack_h2(v0, v1);
                } else {
                    float2 w;
                    w.x = acc[mt][nt][2 * h + 0];
                    w.y = acc[mt][nt][2 * h + 1];
                    *reinterpret_cast<float2*>(Co + o) = w;
                }
            }
        }
    }
}

// ---------------- launch ----------------
extern "C" void kernel_launch(void* const* d_in, const int* in_sizes, int n_in,
                              void* d_out, int out_size) {
    const float* x   = (const float*)d_in[0];
    const int*   ids = (const int*)d_in[1];
    const float* tw  = (const float*)d_in[2];
    const float* W1[2] = {(const float*)d_in[3], (const float*)d_in[7]};
    const float* b1[2] = {(const float*)d_in[4], (const float*)d_in[8]};
    const float* W2[2] = {(const float*)d_in[5], (const float*)d_in[9]};
    const float* b2[2] = {(const float*)d_in[6], (const float*)d_in[10]};
    float* out = (float*)d_out;

    __half *X, *H, *W1h, *W2h;
    float *gate, *P;
    cudaGetSymbolAddress((void**)&X, g_X);
    cudaGetSymbolAddress((void**)&H, g_H);
    cudaGetSymbolAddress((void**)&W1h, g_W1h);
    cudaGetSymbolAddress((void**)&W2h, g_W2h);
    cudaGetSymbolAddress((void**)&P, g_P);
    cudaGetSymbolAddress((void**)&gate, g_gate);

    cudaFuncSetAttribute(moe_gemm<0>, cudaFuncAttributeMaxDynamicSharedMemorySize, SMEM_BYTES);
    cudaFuncSetAttribute(moe_gemm<2>, cudaFuncAttributeMaxDynamicSharedMemorySize, SMEM_BYTES);

    gate_k<<<(NT + 255) / 256, 256>>>(ids, tw, gate);
    {
        size_t n4 = (size_t)NT * DM / 4;
        conv_k<<<(unsigned)((n4 + 255) / 256), 256>>>((const float4*)x, (uint2*)X, n4);
    }
    {
        size_t n4 = (size_t)DM * DF / 4;
        conv_w1<<<dim3((unsigned)((n4 + 255) / 256), 1, 2), 256>>>(
            (const float4*)W1[0], (const float4*)W1[1], (uint2*)W1h);
    }
    {
        size_t n4 = (size_t)DF * DM / 4;
        conv_w2<<<dim3((unsigned)((n4 + 255) / 256), 1, 2), 256>>>(
            (const float4*)W2[0], (const float4*)W2[1], (uint2*)W2h);
    }
    // GEMM1 merged: H [NT][2*DF], N = 16384, K = DM, grid (64, 64)
    moe_gemm<0><<<dim3(2 * DF / BN, NT / BM), NTHR, SMEM_BYTES>>>(
        X, W1h, b1[0], b1[1], gate, nullptr, H,
        DM, DM, 2 * DF, 2 * DF, DF / BN);
    // GEMM2 split-K=2: P[z] = H[:, z*KH:(z+1)*KH] @ W2h[z*KH:(z+1)*KH, :], grid (8, 64, 2)
    moe_gemm<2><<<dim3(DM / BN, NT / BM, 2), NTHR, SMEM_BYTES>>>(
        H, W2h, nullptr, nullptr, gate, P, nullptr,
        KH, 2 * DF, DM, DM, 1 << 30);
    // reduce: out = P0 + P1 + g0*b2_0 + g1*b2_1
    {
        size_t n4 = (size_t)NT * DM / 4;
        reduce_k<<<(unsigned)((n4 + 255) / 256), 256>>>(
            (const float4*)P, (const float4*)(P + (size_t)NT * DM),
            (const float4*)b2[0], (const float4*)b2[1], gate, (float4*)out);
    }
}

// round 16
// speedup vs baseline: 1.0363x; 1.0275x over previous
#include <cuda_runtime.h>
#include <cuda_fp16.h>
#include <cstdint>
#include <math.h>

#define DM 2048
#define DF 8192
#define NT 8192
#define KH 8192   // split-K half of GEMM2's K = 2*DF

// ---------------- scratch ----------------
__device__ __align__(256) __half g_X[(size_t)NT * DM];           // [M][K]
__device__ __align__(256) __half g_H[(size_t)NT * 2 * DF];       // [M][2*DF] gate pre-scaled
__device__ __align__(256) __half g_W1h[(size_t)DM * 2 * DF];     // [DM][2*DF]  (K x N, concat)
__device__ __align__(256) __half g_W2h[(size_t)2 * DF * DM];     // [2*DF][DM]  (K x N, stacked)
__device__ __align__(256) float  g_P[2 * (size_t)NT * DM];       // split-K partials
__device__ float g_gate[2 * NT];

// ---------------- helpers ----------------
__device__ __forceinline__ uint32_t smem_u32(const void* p) {
    uint32_t a;
    asm("{ .reg .u64 t; cvta.to.shared.u64 t, %1; cvt.u32.u64 %0, t; }" : "=r"(a) : "l"(p));
    return a;
}
#define CP_ASYNC16(sa, g) \
    asm volatile("cp.async.cg.shared.global [%0], [%1], 16;" :: "r"(sa), "l"(g))
#define CP_COMMIT() asm volatile("cp.async.commit_group;" ::: "memory")
#define CP_WAIT(n)  asm volatile("cp.async.wait_group %0;" :: "n"(n) : "memory")

#define LDSM_X4(r0, r1, r2, r3, a) \
    asm volatile("ldmatrix.sync.aligned.m8n8.x4.shared.b16 {%0,%1,%2,%3}, [%4];" \
                 : "=r"(r0), "=r"(r1), "=r"(r2), "=r"(r3) : "r"(a))
#define LDSM_X4T(r0, r1, r2, r3, a) \
    asm volatile("ldmatrix.sync.aligned.m8n8.x4.trans.shared.b16 {%0,%1,%2,%3}, [%4];" \
                 : "=r"(r0), "=r"(r1), "=r"(r2), "=r"(r3) : "r"(a))

__device__ __forceinline__ void mma16816(float* d, const uint32_t* a, const uint32_t* b) {
    asm volatile(
        "mma.sync.aligned.m16n8k16.row.col.f32.f16.f16.f32 "
        "{%0,%1,%2,%3}, {%4,%5,%6,%7}, {%8,%9}, {%0,%1,%2,%3};"
        : "+f"(d[0]), "+f"(d[1]), "+f"(d[2]), "+f"(d[3])
        : "r"(a[0]), "r"(a[1]), "r"(a[2]), "r"(a[3]), "r"(b[0]), "r"(b[1]));
}

// A tiles: 128B rows (8x16B segs); B tiles: 512B rows (32x16B segs). XOR-of-row swizzle.
__device__ __forceinline__ uint32_t swzA(uint32_t r, uint32_t s) {
    return (r << 7) + ((s ^ (r & 7)) << 4);
}
__device__ __forceinline__ uint32_t swzB(uint32_t r, uint32_t s) {
    return (r << 9) + ((s ^ (r & 7)) << 4);
}
__device__ __forceinline__ uint32_t pack_h2(float a, float b) {
    __half2 v = __floats2half2_rn(a, b);
    return *reinterpret_cast<uint32_t*>(&v);
}

// fast erf: Abramowitz-Stegun 7.1.26, |err| <= 1.5e-7
__device__ __forceinline__ float erf_fast(float x) {
    float ax = fabsf(x);
    float t = __fdividef(1.0f, fmaf(0.3275911f, ax, 1.0f));
    float p = fmaf(t, 1.061405429f, -1.453152027f);
    p = fmaf(t, p, 1.421413741f);
    p = fmaf(t, p, -0.284496736f);
    p = fmaf(t, p, 0.254829592f);
    p = p * t;
    float e = __expf(-ax * ax);
    return copysignf(fmaf(-p, e, 1.0f), x);
}
__device__ __forceinline__ float gelu_f(float v) {
    return 0.5f * v * (1.0f + erf_fast(v * 0.70710678118654752f));
}

// ---------------- prep kernels (2 float4 per thread) ----------------
__global__ void gate_k(const int* __restrict__ ids, const float* __restrict__ w,
                       float* __restrict__ gate) {
    int i = blockIdx.x * blockDim.x + threadIdx.x;
    if (i >= NT) return;
    int a = ids[2 * i] & 1, b = ids[2 * i + 1] & 1;
    float wa = w[2 * i], wb = w[2 * i + 1];
    gate[i]      = (a ? 0.f : wa) + (b ? 0.f : wb);
    gate[NT + i] = (a ? wa : 0.f) + (b ? wb : 0.f);
}

__device__ __forceinline__ uint2 cvt4(float4 v) {
    uint2 r;
    r.x = pack_h2(v.x, v.y);
    r.y = pack_h2(v.z, v.w);
    return r;
}

__global__ void conv_k(const float4* __restrict__ x4, uint2* __restrict__ o, size_t n4) {
    size_t i = 2 * ((size_t)blockIdx.x * blockDim.x + threadIdx.x);
    if (i >= n4) return;
    float4 v0 = x4[i], v1 = x4[i + 1];
    o[i] = cvt4(v0);
    o[i + 1] = cvt4(v1);
}

// W1_e [DM][DF] f32 -> W1h [DM][2*DF] fp16 at column offset e*DF (blockIdx.z = e)
__global__ void conv_w1(const float4* __restrict__ W0, const float4* __restrict__ W1,
                        uint2* __restrict__ out) {
    size_t i = 2 * ((size_t)blockIdx.x * blockDim.x + threadIdx.x);
    const size_t row_u4 = DF / 4;
    if (i >= (size_t)DM * row_u4) return;
    int e = blockIdx.z;
    const float4* W = e ? W1 : W0;
    float4 v0 = W[i], v1 = W[i + 1];
    size_t k = i / row_u4, n4 = i % row_u4;   // i even, row_u4 even -> same row for i+1
    size_t o = k * (2 * DF / 4) + (size_t)e * (DF / 4) + n4;
    out[o] = cvt4(v0);
    out[o + 1] = cvt4(v1);
}

// W2_e [DF][DM] f32 -> W2h rows [e*DF .. e*DF+DF)
__global__ void conv_w2(const float4* __restrict__ W0, const float4* __restrict__ W1,
                        uint2* __restrict__ out) {
    size_t i = 2 * ((size_t)blockIdx.x * blockDim.x + threadIdx.x);
    if (i >= (size_t)DF * DM / 4) return;
    int e = blockIdx.z;
    const float4* W = e ? W1 : W0;
    float4 v0 = W[i], v1 = W[i + 1];
    size_t o = (size_t)e * (DF * DM / 4) + i;
    out[o] = cvt4(v0);
    out[o + 1] = cvt4(v1);
}

// split-K reduce: out = P0 + P1 + g0*b2_0 + g1*b2_1  (2 float4 per thread)
__global__ void reduce_k(const float4* __restrict__ P0, const float4* __restrict__ P1,
                         const float4* __restrict__ b20, const float4* __restrict__ b21,
                         const float* __restrict__ gate, float4* __restrict__ out) {
    size_t i = 2 * ((size_t)blockIdx.x * blockDim.x + threadIdx.x);
    if (i >= (size_t)NT * DM / 4) return;
    int row = (int)(i / (DM / 4));            // i, i+1 in same row (DM/4 = 512, even)
    int c4  = (int)(i % (DM / 4));
    float g0 = gate[row], g1 = gate[NT + row];
#pragma unroll
    for (int j = 0; j < 2; j++) {
        float4 p = P0[i + j], q = P1[i + j], a = b20[c4 + j], b = b21[c4 + j];
        float4 r;
        r.x = p.x + q.x + g0 * a.x + g1 * b.x;
        r.y = p.y + q.y + g0 * a.y + g1 * b.y;
        r.z = p.z + q.z + g0 * a.z + g1 * b.z;
        r.w = p.w + q.w + g0 * a.w + g1 * b.w;
        out[i + j] = r;
    }
}

// ------------- fp16 mma.sync GEMM: CTA 128x256, BK=64, 512 thr, B in [K][N] -------------
static constexpr int BM = 128, BN = 256, BK = 64;
static constexpr int STAGES = 4;
static constexpr int A_TILE_B = BM * 128;
static constexpr int B_TILE_B = BK * 512;
static constexpr int STAGE_B = A_TILE_B + B_TILE_B;   // 49152
static constexpr int SMEM_BYTES = STAGES * STAGE_B;   // 196608
static constexpr int O_A = 0, O_B = A_TILE_B;
static constexpr int NTHR = 512;

__device__ __forceinline__ void load_A(uint32_t sdst, const __half* __restrict__ g,
                                       int ld, int t) {
#pragma unroll
    for (int i = 0; i < 2; i++) {
        uint32_t idx = t + i * NTHR;
        uint32_t r = idx >> 3, s = idx & 7;
        CP_ASYNC16(sdst + swzA(r, s), g + (size_t)r * ld + s * 8);
    }
}
__device__ __forceinline__ void load_B(uint32_t sdst, const __half* __restrict__ g,
                                       int ld, int t) {
#pragma unroll
    for (int i = 0; i < 4; i++) {
        uint32_t idx = t + i * NTHR;
        uint32_t r = idx >> 5, s = idx & 31;
        CP_ASYNC16(sdst + swzB(r, s), g + (size_t)r * ld + s * 8);
    }
}

// EPI 0 (GEMM1): Ch[row][col] = fp16(gate_e[row]*GELU(v + b1_e[col - e*DF])), e = bx>=n_split
// EPI 2 (GEMM2 split-K): Cf[z][row][col] = raw v; K-range z*KH..(z+1)*KH, reversed bm
template <int EPI>
__global__ void __launch_bounds__(NTHR, 1)
moe_gemm(const __half* __restrict__ A, const __half* __restrict__ B,
         const float* __restrict__ bias0, const float* __restrict__ bias1,
         const float* __restrict__ gate,
         float* __restrict__ Cf, __half* __restrict__ Ch,
         int K, int lda, int ldb, int ldc, int n_split) {
    extern __shared__ char smem[];
    const uint32_t sb = smem_u32(smem);
    const int t = threadIdx.x, wid = t >> 5, lid = t & 31;
    const int wm = wid >> 2, wn = wid & 3;        // 4x4 warps, warp tile 32x64
    const int by = (EPI == 2) ? (gridDim.y - 1 - blockIdx.y) : blockIdx.y;
    const int bm = by * BM, bn = blockIdx.x * BN;
    const int NC = K / BK;
    const int ex = (EPI == 0) ? (blockIdx.x >= n_split) : 0;
    const size_t koff = (EPI == 2) ? (size_t)blockIdx.z * KH : 0;

    const __half* a_g = A + (size_t)bm * lda + koff;
    const __half* b_g = B + koff * ldb + bn;
    float* Co = (EPI == 2) ? Cf + (size_t)blockIdx.z * NT * DM : Cf;

    float acc[2][8][4];
#pragma unroll
    for (int i = 0; i < 2; i++)
#pragma unroll
        for (int j = 0; j < 8; j++)
#pragma unroll
            for (int q = 0; q < 4; q++) acc[i][j][q] = 0.f;

#pragma unroll
    for (int p = 0; p < STAGES - 1; p++) {
        uint32_t st = sb + p * STAGE_B;
        load_A(st + O_A, a_g + p * BK, lda, t);
        load_B(st + O_B, b_g + (size_t)p * BK * ldb, ldb, t);
        CP_COMMIT();
    }

    // A frags (non-trans, [M][K] 128B rows)
    const uint32_t a_r = (uint32_t)(lid & 15);
    const uint32_t a_s = (uint32_t)(lid >> 4);
    // B frags (trans, [K][N] 512B rows)
    const uint32_t bk_r = (uint32_t)((lid & 7) + ((lid >> 3) & 1) * 8);
    const uint32_t bn_s = (uint32_t)(lid >> 4);

    for (int c = 0; c < NC; c++) {
        CP_WAIT(STAGES - 2);
        __syncthreads();
        if (c + STAGES - 1 < NC) {
            int cc = c + STAGES - 1;
            uint32_t st = sb + (cc % STAGES) * STAGE_B;
            load_A(st + O_A, a_g + cc * BK, lda, t);
            load_B(st + O_B, b_g + (size_t)cc * BK * ldb, ldb, t);
        }
        CP_COMMIT();

        const uint32_t st = sb + (c % STAGES) * STAGE_B;
#pragma unroll
        for (int kk = 0; kk < 4; kk++) {
            uint32_t ah[2][4], bh[4][4];
#pragma unroll
            for (int mt = 0; mt < 2; mt++) {
                uint32_t off = swzA(wm * 32 + mt * 16 + a_r, kk * 2 + a_s);
                LDSM_X4(ah[mt][0], ah[mt][1], ah[mt][2], ah[mt][3], st + O_A + off);
            }
#pragma unroll
            for (int p = 0; p < 4; p++) {   // 4 n16 groups = warp's 64 cols
                uint32_t off = swzB(kk * 16 + bk_r, wn * 8 + p * 2 + bn_s);
                LDSM_X4T(bh[p][0], bh[p][1], bh[p][2], bh[p][3], st + O_B + off);
            }
#pragma unroll
            for (int mt = 0; mt < 2; mt++)
#pragma unroll
                for (int nt = 0; nt < 8; nt++)
                    mma16816(acc[mt][nt], ah[mt], &bh[nt >> 1][(nt & 1) << 1]);
        }
    }

    // ---------------- epilogue ----------------
    const int lr = lid >> 2, lc = (lid & 3) << 1;
#pragma unroll
    for (int mt = 0; mt < 2; mt++) {
        int row0 = bm + wm * 32 + mt * 16 + lr;
        float ga0 = 0.f, ga1 = 0.f;
        if (EPI == 0) {
            ga0 = gate[ex * NT + row0];
            ga1 = gate[ex * NT + row0 + 8];
        }
#pragma unroll
        for (int nt = 0; nt < 8; nt++) {
            int col = bn + wn * 64 + nt * 8 + lc;
            float b00 = 0.f, b01 = 0.f;
            if (EPI == 0) {
                const float* ba = ex ? bias1 : bias0;
                int bc = col - ex * DF;
                b00 = ba[bc]; b01 = ba[bc + 1];
            }
#pragma unroll
            for (int h = 0; h < 2; h++) {
                int row = row0 + h * 8;
                size_t o = (size_t)row * ldc + col;
                if (EPI == 0) {
                    float g = h ? ga1 : ga0;
                    float v0 = g * gelu_f(acc[mt][nt][2 * h + 0] + b00);
                    float v1 = g * gelu_f(acc[mt][nt][2 * h + 1] + b01);
                    *reinterpret_cast<uint32_t*>(Ch + o) = pack_h2(v0, v1);
                } else {
                    float2 w;
                    w.x = acc[mt][nt][2 * h + 0];
                    w.y = acc[mt][nt][2 * h + 1];
                    *reinterpret_cast<float2*>(Co + o) = w;
                }
            }
        }
    }
}

// ---------------- launch ----------------
extern "C" void kernel_launch(void* const* d_in, const int* in_sizes, int n_in,
                              void* d_out, int out_size) {
    const float* x   = (const float*)d_in[0];
    const int*   ids = (const int*)d_in[1];
    const float* tw  = (const float*)d_in[2];
    const float* W1[2] = {(const float*)d_in[3], (const float*)d_in[7]};
    const float* b1[2] = {(const float*)d_in[4], (const float*)d_in[8]};
    const float* W2[2] = {(const float*)d_in[5], (const float*)d_in[9]};
    const float* b2[2] = {(const float*)d_in[6], (const float*)d_in[10]};
    float* out = (float*)d_out;

    __half *X, *H, *W1h, *W2h;
    float *gate, *P;
    cudaGetSymbolAddress((void**)&X, g_X);
    cudaGetSymbolAddress((void**)&H, g_H);
    cudaGetSymbolAddress((void**)&W1h, g_W1h);
    cudaGetSymbolAddress((void**)&W2h, g_W2h);
    cudaGetSymbolAddress((void**)&P, g_P);
    cudaGetSymbolAddress((void**)&gate, g_gate);

    cudaFuncSetAttribute(moe_gemm<0>, cudaFuncAttributeMaxDynamicSharedMemorySize, SMEM_BYTES);
    cudaFuncSetAttribute(moe_gemm<2>, cudaFuncAttributeMaxDynamicSharedMemorySize, SMEM_BYTES);

    gate_k<<<(NT + 255) / 256, 256>>>(ids, tw, gate);
    {
        size_t n4 = (size_t)NT * DM / 4;          // 2 float4 per thread
        conv_k<<<(unsigned)((n4 / 2 + 255) / 256), 256>>>((const float4*)x, (uint2*)X, n4);
    }
    {
        size_t nt2 = (size_t)DM * DF / 8;         // threads per expert
        conv_w1<<<dim3((unsigned)((nt2 + 255) / 256), 1, 2), 256>>>(
            (const float4*)W1[0], (const float4*)W1[1], (uint2*)W1h);
    }
    {
        size_t nt2 = (size_t)DF * DM / 8;
        conv_w2<<<dim3((unsigned)((nt2 + 255) / 256), 1, 2), 256>>>(
            (const float4*)W2[0], (const float4*)W2[1], (uint2*)W2h);
    }
    // GEMM1 merged: H [NT][2*DF], N = 16384, K = DM, grid (64, 64)
    moe_gemm<0><<<dim3(2 * DF / BN, NT / BM), NTHR, SMEM_BYTES>>>(
        X, W1h, b1[0], b1[1], gate, nullptr, H,
        DM, DM, 2 * DF, 2 * DF, DF / BN);
    // GEMM2 split-K=2: P[z] = H[:, z*KH:(z+1)*KH] @ W2h[z*KH:(z+1)*KH, :], grid (8, 64, 2)
    moe_gemm<2><<<dim3(DM / BN, NT / BM, 2), NTHR, SMEM_BYTES>>>(
        H, W2h, nullptr, nullptr, gate, P, nullptr,
        KH, 2 * DF, DM, DM, 1 << 30);
    // reduce: out = P0 + P1 + g0*b2_0 + g1*b2_1
    {
        size_t nt2 = (size_t)NT * DM / 8;
        reduce_k<<<(unsigned)((nt2 + 255) / 256), 256>>>(
            (const float4*)P, (const float4*)(P + (size_t)NT * DM),
            (const float4*)b2[0], (const float4*)b2[1], gate, (float4*)out);
    }
}

// round 17
// speedup vs baseline: 1.1017x; 1.0631x over previous
#include <cuda_runtime.h>
#include <cuda_fp16.h>
#include <cstdint>
#include <math.h>

#define DM 2048
#define DF 8192
#define NT 8192
#define KH 8192   // split-K half of GEMM2's K = 2*DF

// ---------------- scratch ----------------
__device__ __align__(256) __half g_X[(size_t)NT * DM];           // [M][K]
__device__ __align__(256) __half g_H[(size_t)NT * 2 * DF];       // [M][2*DF] gate pre-scaled
__device__ __align__(256) __half g_W1h[(size_t)DM * 2 * DF];     // [DM][2*DF]  (K x N, concat)
__device__ __align__(256) __half g_W2h[(size_t)2 * DF * DM];     // [2*DF][DM]  (K x N, stacked)
__device__ __align__(256) float  g_P[2 * (size_t)NT * DM];       // split-K partials
__device__ float g_gate[2 * NT];

// ---------------- helpers ----------------
__device__ __forceinline__ uint32_t smem_u32(const void* p) {
    uint32_t a;
    asm("{ .reg .u64 t; cvta.to.shared.u64 t, %1; cvt.u32.u64 %0, t; }" : "=r"(a) : "l"(p));
    return a;
}
#define CP_ASYNC16(sa, g) \
    asm volatile("cp.async.cg.shared.global [%0], [%1], 16;" :: "r"(sa), "l"(g))
#define CP_COMMIT() asm volatile("cp.async.commit_group;" ::: "memory")
#define CP_WAIT(n)  asm volatile("cp.async.wait_group %0;" :: "n"(n) : "memory")

#define LDSM_X4(r0, r1, r2, r3, a) \
    asm volatile("ldmatrix.sync.aligned.m8n8.x4.shared.b16 {%0,%1,%2,%3}, [%4];" \
                 : "=r"(r0), "=r"(r1), "=r"(r2), "=r"(r3) : "r"(a))
#define LDSM_X4T(r0, r1, r2, r3, a) \
    asm volatile("ldmatrix.sync.aligned.m8n8.x4.trans.shared.b16 {%0,%1,%2,%3}, [%4];" \
                 : "=r"(r0), "=r"(r1), "=r"(r2), "=r"(r3) : "r"(a))

__device__ __forceinline__ void mma16816(float* d, const uint32_t* a, const uint32_t* b) {
    asm volatile(
        "mma.sync.aligned.m16n8k16.row.col.f32.f16.f16.f32 "
        "{%0,%1,%2,%3}, {%4,%5,%6,%7}, {%8,%9}, {%0,%1,%2,%3};"
        : "+f"(d[0]), "+f"(d[1]), "+f"(d[2]), "+f"(d[3])
        : "r"(a[0]), "r"(a[1]), "r"(a[2]), "r"(a[3]), "r"(b[0]), "r"(b[1]));
}

// A tiles: 256B rows (16x16B segs); B tiles: 512B rows (32x16B segs). XOR-of-row swizzle.
__device__ __forceinline__ uint32_t swzA(uint32_t r, uint32_t s) {
    return (r << 8) + ((s ^ (r & 7)) << 4);
}
__device__ __forceinline__ uint32_t swzB(uint32_t r, uint32_t s) {
    return (r << 9) + ((s ^ (r & 7)) << 4);
}
__device__ __forceinline__ uint32_t pack_h2(float a, float b) {
    __half2 v = __floats2half2_rn(a, b);
    return *reinterpret_cast<uint32_t*>(&v);
}

// fast erf: Abramowitz-Stegun 7.1.26, |err| <= 1.5e-7
__device__ __forceinline__ float erf_fast(float x) {
    float ax = fabsf(x);
    float t = __fdividef(1.0f, fmaf(0.3275911f, ax, 1.0f));
    float p = fmaf(t, 1.061405429f, -1.453152027f);
    p = fmaf(t, p, 1.421413741f);
    p = fmaf(t, p, -0.284496736f);
    p = fmaf(t, p, 0.254829592f);
    p = p * t;
    float e = __expf(-ax * ax);
    return copysignf(fmaf(-p, e, 1.0f), x);
}
__device__ __forceinline__ float gelu_f(float v) {
    return 0.5f * v * (1.0f + erf_fast(v * 0.70710678118654752f));
}

// ---------------- prep kernels (2 float4 per thread) ----------------
__global__ void gate_k(const int* __restrict__ ids, const float* __restrict__ w,
                       float* __restrict__ gate) {
    int i = blockIdx.x * blockDim.x + threadIdx.x;
    if (i >= NT) return;
    int a = ids[2 * i] & 1, b = ids[2 * i + 1] & 1;
    float wa = w[2 * i], wb = w[2 * i + 1];
    gate[i]      = (a ? 0.f : wa) + (b ? 0.f : wb);
    gate[NT + i] = (a ? wa : 0.f) + (b ? wb : 0.f);
}

__device__ __forceinline__ uint2 cvt4(float4 v) {
    uint2 r;
    r.x = pack_h2(v.x, v.y);
    r.y = pack_h2(v.z, v.w);
    return r;
}

__global__ void conv_k(const float4* __restrict__ x4, uint2* __restrict__ o, size_t n4) {
    size_t i = 2 * ((size_t)blockIdx.x * blockDim.x + threadIdx.x);
    if (i >= n4) return;
    float4 v0 = x4[i], v1 = x4[i + 1];
    o[i] = cvt4(v0);
    o[i + 1] = cvt4(v1);
}

// W1_e [DM][DF] f32 -> W1h [DM][2*DF] fp16 at column offset e*DF (blockIdx.z = e)
__global__ void conv_w1(const float4* __restrict__ W0, const float4* __restrict__ W1,
                        uint2* __restrict__ out) {
    size_t i = 2 * ((size_t)blockIdx.x * blockDim.x + threadIdx.x);
    const size_t row_u4 = DF / 4;
    if (i >= (size_t)DM * row_u4) return;
    int e = blockIdx.z;
    const float4* W = e ? W1 : W0;
    float4 v0 = W[i], v1 = W[i + 1];
    size_t k = i / row_u4, n4 = i % row_u4;
    size_t o = k * (2 * DF / 4) + (size_t)e * (DF / 4) + n4;
    out[o] = cvt4(v0);
    out[o + 1] = cvt4(v1);
}

// W2_e [DF][DM] f32 -> W2h rows [e*DF .. e*DF+DF)
__global__ void conv_w2(const float4* __restrict__ W0, const float4* __restrict__ W1,
                        uint2* __restrict__ out) {
    size_t i = 2 * ((size_t)blockIdx.x * blockDim.x + threadIdx.x);
    if (i >= (size_t)DF * DM / 4) return;
    int e = blockIdx.z;
    const float4* W = e ? W1 : W0;
    float4 v0 = W[i], v1 = W[i + 1];
    size_t o = (size_t)e * (DF * DM / 4) + i;
    out[o] = cvt4(v0);
    out[o + 1] = cvt4(v1);
}

// split-K reduce: out = P0 + P1 (bias pre-folded into z=0 partial); 2 float4/thread
__global__ void reduce_k(const float4* __restrict__ P0, const float4* __restrict__ P1,
                         float4* __restrict__ out) {
    size_t i = 2 * ((size_t)blockIdx.x * blockDim.x + threadIdx.x);
    if (i >= (size_t)NT * DM / 4) return;
#pragma unroll
    for (int j = 0; j < 2; j++) {
        float4 p = P0[i + j], q = P1[i + j];
        float4 r;
        r.x = p.x + q.x;
        r.y = p.y + q.y;
        r.z = p.z + q.z;
        r.w = p.w + q.w;
        out[i + j] = r;
    }
}

// ------------- fp16 mma.sync GEMM: CTA 128x256, BK=128, 2 stages, 512 thr -------------
static constexpr int BM = 128, BN = 256, BK = 128;
static constexpr int STAGES = 2;
static constexpr int A_TILE_B = BM * 256;             // [M=128][K=128], 256B rows = 32 KB
static constexpr int B_TILE_B = BK * 512;             // [K=128][N=256], 512B rows = 64 KB
static constexpr int STAGE_B = A_TILE_B + B_TILE_B;   // 98304
static constexpr int SMEM_BYTES = STAGES * STAGE_B;   // 196608
static constexpr int O_A = 0, O_B = A_TILE_B;
static constexpr int NTHR = 512;

__device__ __forceinline__ void load_A(uint32_t sdst, const __half* __restrict__ g,
                                       int ld, int t) {
#pragma unroll
    for (int i = 0; i < 4; i++) {                 // 128 rows x 16 segs / 512 thr
        uint32_t idx = t + i * NTHR;
        uint32_t r = idx >> 4, s = idx & 15;
        CP_ASYNC16(sdst + swzA(r, s), g + (size_t)r * ld + s * 8);
    }
}
__device__ __forceinline__ void load_B(uint32_t sdst, const __half* __restrict__ g,
                                       int ld, int t) {
#pragma unroll
    for (int i = 0; i < 8; i++) {                 // 128 rows x 32 segs / 512 thr
        uint32_t idx = t + i * NTHR;
        uint32_t r = idx >> 5, s = idx & 31;
        CP_ASYNC16(sdst + swzB(r, s), g + (size_t)r * ld + s * 8);
    }
}

// EPI 0 (GEMM1): Ch[row][col] = fp16(gate_e[row]*GELU(v + b1_e[col - e*DF])), e = bx>=n_split
// EPI 2 (GEMM2 split-K): Cf[z][row][col] = v (+ g0*bias0 + g1*bias1 when z==0); reversed bm
template <int EPI>
__global__ void __launch_bounds__(NTHR, 1)
moe_gemm(const __half* __restrict__ A, const __half* __restrict__ B,
         const float* __restrict__ bias0, const float* __restrict__ bias1,
         const float* __restrict__ gate,
         float* __restrict__ Cf, __half* __restrict__ Ch,
         int K, int lda, int ldb, int ldc, int n_split) {
    extern __shared__ char smem[];
    const uint32_t sb = smem_u32(smem);
    const int t = threadIdx.x, wid = t >> 5, lid = t & 31;
    const int wm = wid >> 2, wn = wid & 3;        // 4x4 warps, warp tile 32x64
    const int by = (EPI == 2) ? (gridDim.y - 1 - blockIdx.y) : blockIdx.y;
    const int bm = by * BM, bn = blockIdx.x * BN;
    const int NC = K / BK;
    const int ex = (EPI == 0) ? (blockIdx.x >= n_split) : 0;
    const size_t koff = (EPI == 2) ? (size_t)blockIdx.z * KH : 0;

    const __half* a_g = A + (size_t)bm * lda + koff;
    const __half* b_g = B + koff * ldb + bn;
    float* Co = (EPI == 2) ? Cf + (size_t)blockIdx.z * NT * DM : Cf;

    float acc[2][8][4];
#pragma unroll
    for (int i = 0; i < 2; i++)
#pragma unroll
        for (int j = 0; j < 8; j++)
#pragma unroll
            for (int q = 0; q < 4; q++) acc[i][j][q] = 0.f;

    // prologue: preload stage 0
    load_A(sb + O_A, a_g, lda, t);
    load_B(sb + O_B, b_g, ldb, t);
    CP_COMMIT();

    // A frags (non-trans, [M][K] 256B rows)
    const uint32_t a_r = (uint32_t)(lid & 15);
    const uint32_t a_s = (uint32_t)(lid >> 4);
    // B frags (trans, [K][N] 512B rows)
    const uint32_t bk_r = (uint32_t)((lid & 7) + ((lid >> 3) & 1) * 8);
    const uint32_t bn_s = (uint32_t)(lid >> 4);

    for (int c = 0; c < NC; c++) {
        CP_WAIT(0);
        __syncthreads();
        if (c + 1 < NC) {
            uint32_t st = sb + ((c + 1) & 1) * STAGE_B;
            load_A(st + O_A, a_g + (c + 1) * BK, lda, t);
            load_B(st + O_B, b_g + (size_t)(c + 1) * BK * ldb, ldb, t);
            CP_COMMIT();
        }

        const uint32_t st = sb + (c & 1) * STAGE_B;
#pragma unroll
        for (int kk = 0; kk < 8; kk++) {          // 8 k16 steps in BK=128
            uint32_t ah[2][4], bh[4][4];
#pragma unroll
            for (int mt = 0; mt < 2; mt++) {
                uint32_t off = swzA(wm * 32 + mt * 16 + a_r, kk * 2 + a_s);
                LDSM_X4(ah[mt][0], ah[mt][1], ah[mt][2], ah[mt][3], st + O_A + off);
            }
#pragma unroll
            for (int p = 0; p < 4; p++) {         // 4 n16 groups = warp's 64 cols
                uint32_t off = swzB(kk * 16 + bk_r, wn * 8 + p * 2 + bn_s);
                LDSM_X4T(bh[p][0], bh[p][1], bh[p][2], bh[p][3], st + O_B + off);
            }
#pragma unroll
            for (int mt = 0; mt < 2; mt++)
#pragma unroll
                for (int nt = 0; nt < 8; nt++)
                    mma16816(acc[mt][nt], ah[mt], &bh[nt >> 1][(nt & 1) << 1]);
        }
    }

    // ---------------- epilogue ----------------
    const int lr = lid >> 2, lc = (lid & 3) << 1;
    const bool add_bias2 = (EPI == 2) && (blockIdx.z == 0);
#pragma unroll
    for (int mt = 0; mt < 2; mt++) {
        int row0 = bm + wm * 32 + mt * 16 + lr;
        float ga0 = 0.f, ga1 = 0.f, gb0 = 0.f, gb1 = 0.f;
        if (EPI == 0) {
            ga0 = gate[ex * NT + row0];
            ga1 = gate[ex * NT + row0 + 8];
        } else if (add_bias2) {
            ga0 = gate[row0];       ga1 = gate[row0 + 8];
            gb0 = gate[NT + row0];  gb1 = gate[NT + row0 + 8];
        }
#pragma unroll
        for (int nt = 0; nt < 8; nt++) {
            int col = bn + wn * 64 + nt * 8 + lc;
            float b00 = 0.f, b01 = 0.f, b10 = 0.f, b11 = 0.f;
            if (EPI == 0) {
                const float* ba = ex ? bias1 : bias0;
                int bc = col - ex * DF;
                b00 = ba[bc]; b01 = ba[bc + 1];
            } else if (add_bias2) {
                b00 = bias0[col]; b01 = bias0[col + 1];
                b10 = bias1[col]; b11 = bias1[col + 1];
            }
#pragma unroll
            for (int h = 0; h < 2; h++) {
                int row = row0 + h * 8;
                size_t o = (size_t)row * ldc + col;
                if (EPI == 0) {
                    float g = h ? ga1 : ga0;
                    float v0 = g * gelu_f(acc[mt][nt][2 * h + 0] + b00);
                    float v1 = g * gelu_f(acc[mt][nt][2 * h + 1] + b01);
                    *reinterpret_cast<uint32_t*>(Ch + o) = pack_h2(v0, v1);
                } else {
                    float2 w;
                    w.x = acc[mt][nt][2 * h + 0];
                    w.y = acc[mt][nt][2 * h + 1];
                    if (add_bias2) {
                        float g0 = h ? ga1 : ga0, g1 = h ? gb1 : gb0;
                        w.x += g0 * b00 + g1 * b10;
                        w.y += g0 * b01 + g1 * b11;
                    }
                    *reinterpret_cast<float2*>(Co + o) = w;
                }
            }
        }
    }
}

// ---------------- launch ----------------
extern "C" void kernel_launch(void* const* d_in, const int* in_sizes, int n_in,
                              void* d_out, int out_size) {
    const float* x   = (const float*)d_in[0];
    const int*   ids = (const int*)d_in[1];
    const float* tw  = (const float*)d_in[2];
    const float* W1[2] = {(const float*)d_in[3], (const float*)d_in[7]};
    const float* b1[2] = {(const float*)d_in[4], (const float*)d_in[8]};
    const float* W2[2] = {(const float*)d_in[5], (const float*)d_in[9]};
    const float* b2[2] = {(const float*)d_in[6], (const float*)d_in[10]};
    float* out = (float*)d_out;

    __half *X, *H, *W1h, *W2h;
    float *gate, *P;
    cudaGetSymbolAddress((void**)&X, g_X);
    cudaGetSymbolAddress((void**)&H, g_H);
    cudaGetSymbolAddress((void**)&W1h, g_W1h);
    cudaGetSymbolAddress((void**)&W2h, g_W2h);
    cudaGetSymbolAddress((void**)&P, g_P);
    cudaGetSymbolAddress((void**)&gate, g_gate);

    cudaFuncSetAttribute(moe_gemm<0>, cudaFuncAttributeMaxDynamicSharedMemorySize, SMEM_BYTES);
    cudaFuncSetAttribute(moe_gemm<2>, cudaFuncAttributeMaxDynamicSharedMemorySize, SMEM_BYTES);

    gate_k<<<(NT + 255) / 256, 256>>>(ids, tw, gate);
    {
        size_t n4 = (size_t)NT * DM / 4;
        conv_k<<<(unsigned)((n4 / 2 + 255) / 256), 256>>>((const float4*)x, (uint2*)X, n4);
    }
    {
        size_t nt2 = (size_t)DM * DF / 8;
        conv_w1<<<dim3((unsigned)((nt2 + 255) / 256), 1, 2), 256>>>(
            (const float4*)W1[0], (const float4*)W1[1], (uint2*)W1h);
    }
    {
        size_t nt2 = (size_t)DF * DM / 8;
        conv_w2<<<dim3((unsigned)((nt2 + 255) / 256), 1, 2), 256>>>(
            (const float4*)W2[0], (const float4*)W2[1], (uint2*)W2h);
    }
    // GEMM1 merged: H [NT][2*DF], N = 16384, K = DM, grid (64, 64)
    moe_gemm<0><<<dim3(2 * DF / BN, NT / BM), NTHR, SMEM_BYTES>>>(
        X, W1h, b1[0], b1[1], gate, nullptr, H,
        DM, DM, 2 * DF, 2 * DF, DF / BN);
    // GEMM2 split-K=2: P[z] = H[:, z*KH:(z+1)*KH] @ W2h[z*KH:(z+1)*KH, :] (+bias at z=0)
    moe_gemm<2><<<dim3(DM / BN, NT / BM, 2), NTHR, SMEM_BYTES>>>(
        H, W2h, b2[0], b2[1], gate, P, nullptr,
        KH, 2 * DF, DM, DM, 1 << 30);
    // reduce: out = P0 + P1
    {
        size_t nt2 = (size_t)NT * DM / 8;
        reduce_k<<<(unsigned)((nt2 + 255) / 256), 256>>>(
            (const float4*)P, (const float4*)(P + (size_t)NT * DM), (float4*)out);
    }
}